// round 10
// baseline (speedup 1.0000x reference)
#include <cuda_runtime.h>
#include <cuda_bf16.h>
#include <cstdint>
#include <math.h>

// ---------------- problem constants ----------------
constexpr int CB = 2;        // batch
constexpr int CS = 2048;     // seq
constexpr int CD = 1024;     // model dim
constexpr int CH = 8;        // heads
constexpr int CHD = 128;     // head dim
constexpr int CM = CB * CS;  // 4096 rows

// ---------------- scratch (device globals; no allocations allowed) ----------
__device__ float g_Sf[CB * CS * CD];  // self_force = x @ Wself^T (fp32)

__device__ __nv_bfloat16 g_xh[CM * CD];
__device__ __nv_bfloat16 g_xl[CM * CD];
__device__ __nv_bfloat16 g_wh[4][CD * CD];
__device__ __nv_bfloat16 g_wl[4][CD * CD];

__device__ __nv_bfloat16 g_Kh[CB * CS * CD];
__device__ __nv_bfloat16 g_Kl[CB * CS * CD];
__device__ __nv_bfloat16 g_Vb[CB * CS * CD];

// ============================================================================
// PTX helpers (family-common sm_80+ only; tcgen05 unavailable on this ptxas)
// ============================================================================
__device__ __forceinline__ uint32_t smem_u32(const void* p) {
    uint32_t a;
    asm("{ .reg .u64 t; cvta.to.shared.u64 t, %1; cvt.u32.u64 %0, t; }" : "=r"(a) : "l"(p));
    return a;
}
__device__ __forceinline__ void cp16(uint32_t dst, const void* src) {
    asm volatile("cp.async.cg.shared.global [%0], [%1], 16;" :: "r"(dst), "l"(src) : "memory");
}
#define CP_COMMIT() asm volatile("cp.async.commit_group;" ::: "memory")
#define CP_WAIT0()  asm volatile("cp.async.wait_group 0;" ::: "memory")
#define CP_WAIT1()  asm volatile("cp.async.wait_group 1;" ::: "memory")
#define CP_WAIT2()  asm volatile("cp.async.wait_group 2;" ::: "memory")

__device__ __forceinline__ void ldsm4(uint32_t* r, uint32_t addr) {
    asm volatile("ldmatrix.sync.aligned.m8n8.x4.shared.b16 {%0,%1,%2,%3}, [%4];"
                 : "=r"(r[0]), "=r"(r[1]), "=r"(r[2]), "=r"(r[3]) : "r"(addr));
}
__device__ __forceinline__ void ldsm4t(uint32_t* r, uint32_t addr) {
    asm volatile("ldmatrix.sync.aligned.m8n8.x4.trans.shared.b16 {%0,%1,%2,%3}, [%4];"
                 : "=r"(r[0]), "=r"(r[1]), "=r"(r[2]), "=r"(r[3]) : "r"(addr));
}
__device__ __forceinline__ void mma16816(float* d, const uint32_t* a, const uint32_t* b) {
    asm volatile(
        "mma.sync.aligned.m16n8k16.row.col.f32.bf16.bf16.f32 "
        "{%0,%1,%2,%3}, {%4,%5,%6,%7}, {%8,%9}, {%0,%1,%2,%3};\n"
        : "+f"(d[0]), "+f"(d[1]), "+f"(d[2]), "+f"(d[3])
        : "r"(a[0]), "r"(a[1]), "r"(a[2]), "r"(a[3]), "r"(b[0]), "r"(b[1]));
}

// ---- fp32 -> bf16 hi/lo helpers --------------------------------------------
__device__ __forceinline__ void split4(float4 v, __nv_bfloat162* hi2, __nv_bfloat162* lo2,
                                       size_t i2) {
    __nv_bfloat16 h0 = __float2bfloat16_rn(v.x), h1 = __float2bfloat16_rn(v.y);
    __nv_bfloat16 h2 = __float2bfloat16_rn(v.z), h3 = __float2bfloat16_rn(v.w);
    __nv_bfloat16 l0 = __float2bfloat16_rn(v.x - __bfloat162float(h0));
    __nv_bfloat16 l1 = __float2bfloat16_rn(v.y - __bfloat162float(h1));
    __nv_bfloat16 l2 = __float2bfloat16_rn(v.z - __bfloat162float(h2));
    __nv_bfloat16 l3 = __float2bfloat16_rn(v.w - __bfloat162float(h3));
    hi2[i2]     = __nv_bfloat162(h0, h1);
    hi2[i2 + 1] = __nv_bfloat162(h2, h3);
    lo2[i2]     = __nv_bfloat162(l0, l1);
    lo2[i2 + 1] = __nv_bfloat162(l2, l3);
}
__device__ __forceinline__ void store_split2(__nv_bfloat16* H, __nv_bfloat16* L,
                                             size_t off, float a, float b) {
    __nv_bfloat16 h0 = __float2bfloat16_rn(a), h1 = __float2bfloat16_rn(b);
    __nv_bfloat16 l0 = __float2bfloat16_rn(a - __bfloat162float(h0));
    __nv_bfloat16 l1 = __float2bfloat16_rn(b - __bfloat162float(h1));
    *(__nv_bfloat162*)(H + off) = __nv_bfloat162(h0, h1);
    *(__nv_bfloat162*)(L + off) = __nv_bfloat162(l0, l1);
}

// ============================================================================
// prep: one kernel splitting x and all 4 weights into bf16 hi/lo
// ============================================================================
constexpr size_t XQ = (size_t)CM * CD / 4;
constexpr size_t WQ = (size_t)CD * CD / 4;
__global__ __launch_bounds__(256) void prep(const float* __restrict__ x,
                                            const float* __restrict__ Wk,
                                            const float* __restrict__ Wv,
                                            const float* __restrict__ Ws,
                                            const float* __restrict__ Wo) {
    size_t i = (size_t)blockIdx.x * 256 + threadIdx.x;
    if (i < XQ) {
        split4(((const float4*)x)[i], (__nv_bfloat162*)g_xh, (__nv_bfloat162*)g_xl, i * 2);
    } else {
        size_t j = i - XQ;
        int w = (int)(j / WQ);
        size_t o = j % WQ;
        const float* W = (w == 0) ? Wk : (w == 1) ? Wv : (w == 2) ? Ws : Wo;
        split4(((const float4*)W)[o], (__nv_bfloat162*)g_wh[w], (__nv_bfloat162*)g_wl[w], o * 2);
    }
}

// ============================================================================
// HMMA bf16-split GEMM core:  C = A @ W^T, 128x128 CTA tile, 4 warps of 64x64.
// K-chunk 16, 4-stage cp.async ring, wait_group 2 => 3 chunks of lookahead.
// 48B smem rows (32B data + 16B pad): (3*row) mod 8 granule permutation gives
// conflict-free ldmatrix. F3: 3-term split (AhBh+AhBl+AlBh); else plain bf16.
// ============================================================================
constexpr int RS2 = 48;
constexpr int TILE2 = 128 * RS2;          // 6144 B
constexpr int STAGE2 = 4 * TILE2;         // 24576 B (Ah, Al, Bh, Bl slots)
constexpr int G_SMEM = 4 * STAGE2;        // 98304 B

template <bool F3>
__device__ __forceinline__ void g_load16(uint32_t st_, int m0, int n0, int k0, int tid,
                                         const __nv_bfloat16* Ah_, const __nv_bfloat16* Al_,
                                         const __nv_bfloat16* Bh_, const __nv_bfloat16* Bl_) {
    const int lr = tid >> 1, lc = tid & 1;
#pragma unroll
    for (int rr = 0; rr < 2; rr++) {
        const int row = lr + rr * 64;
        const uint32_t so = (uint32_t)(row * RS2 + lc * 16);
        const size_t gA = (size_t)(m0 + row) * CD + k0 + lc * 8;
        const size_t gB = (size_t)(n0 + row) * CD + k0 + lc * 8;
        cp16(st_ + 0 * TILE2 + so, Ah_ + gA);
        cp16(st_ + 2 * TILE2 + so, Bh_ + gB);
        if (F3) {
            cp16(st_ + 1 * TILE2 + so, Al_ + gA);
            cp16(st_ + 3 * TILE2 + so, Bl_ + gB);
        }
    }
    CP_COMMIT();
}

template <bool F3>
__device__ __forceinline__ void gemm_core(uint32_t sb, int tid, int lane, int wm, int wn,
                                          int m0, int n0,
                                          const __nv_bfloat16* Ah_, const __nv_bfloat16* Al_,
                                          const __nv_bfloat16* Bh_, const __nv_bfloat16* Bl_,
                                          float acc[4][8][4]) {
#pragma unroll
    for (int i = 0; i < 4; i++)
#pragma unroll
        for (int j = 0; j < 8; j++)
#pragma unroll
            for (int r = 0; r < 4; r++) acc[i][j][r] = 0.f;

    constexpr int NC = CD / 16;  // 64 chunks
    g_load16<F3>(sb + 0 * STAGE2, m0, n0, 0, tid, Ah_, Al_, Bh_, Bl_);
    g_load16<F3>(sb + 1 * STAGE2, m0, n0, 16, tid, Ah_, Al_, Bh_, Bl_);
    g_load16<F3>(sb + 2 * STAGE2, m0, n0, 32, tid, Ah_, Al_, Bh_, Bl_);

    for (int c = 0; c < NC; c++) {
        CP_WAIT2();        // stage c complete (3 groups may be outstanding)
        __syncthreads();
        if (c + 3 < NC)
            g_load16<F3>(sb + ((c + 3) & 3) * STAGE2, m0, n0, (c + 3) * 16, tid,
                         Ah_, Al_, Bh_, Bl_);
        else
            CP_COMMIT();   // empty group keeps the wait_group count uniform

        const uint32_t st = sb + (c & 3) * STAGE2;
        uint32_t bh[16], bl[16];
#pragma unroll
        for (int j4 = 0; j4 < 4; j4++) {
            uint32_t off = (uint32_t)((wn + j4 * 16 + (lane & 15)) * RS2 + (lane >> 4) * 16);
            ldsm4(bh + j4 * 4, st + 2 * TILE2 + off);
            if (F3) ldsm4(bl + j4 * 4, st + 3 * TILE2 + off);
        }
#pragma unroll
        for (int i = 0; i < 4; i++) {
            uint32_t aoff = (uint32_t)((wm + i * 16 + (lane & 15)) * RS2 + (lane >> 4) * 16);
            uint32_t ah[4], al[4];
            ldsm4(ah, st + 0 * TILE2 + aoff);
            if (F3) ldsm4(al, st + 1 * TILE2 + aoff);
#pragma unroll
            for (int j = 0; j < 8; j++) {
                uint32_t b2[2] = {bh[(j >> 1) * 4 + (j & 1)], bh[(j >> 1) * 4 + 2 + (j & 1)]};
                mma16816(acc[i][j], ah, b2);
            }
            if (F3) {
#pragma unroll
                for (int j = 0; j < 8; j++) {
                    uint32_t b2[2] = {bl[(j >> 1) * 4 + (j & 1)], bl[(j >> 1) * 4 + 2 + (j & 1)]};
                    mma16816(acc[i][j], ah, b2);
                }
#pragma unroll
                for (int j = 0; j < 8; j++) {
                    uint32_t b2[2] = {bh[(j >> 1) * 4 + (j & 1)], bh[(j >> 1) * 4 + 2 + (j & 1)]};
                    mma16816(acc[i][j], al, b2);
                }
            }
        }
        // no trailing barrier: the load issued in iter c+1 (after its top sync)
        // is the first writer of the buffer compute(c) just read.
    }
}

// ---- the 3 projection GEMMs in one launch ----------------------------------
__global__ __launch_bounds__(128, 2) void gemm3() {
    extern __shared__ __align__(128) char smem[];
    const uint32_t sb = smem_u32(smem);
    const int tid = threadIdx.x, wid = tid >> 5, lane = tid & 31;
    const int mode = (int)(blockIdx.x >> 3);
    const int n0 = (int)(blockIdx.x & 7) * 128;
    const int m0 = (int)blockIdx.y * 128;
    const int wm = (wid >> 1) * 64;
    const int wn = (wid & 1) * 64;

    float acc[4][8][4];
    if (mode == 1)
        gemm_core<false>(sb, tid, lane, wm, wn, m0, n0, g_xh, g_xl, g_wh[1], g_wl[1], acc);
    else if (mode == 0)
        gemm_core<true>(sb, tid, lane, wm, wn, m0, n0, g_xh, g_xl, g_wh[0], g_wl[0], acc);
    else
        gemm_core<true>(sb, tid, lane, wm, wn, m0, n0, g_xh, g_xl, g_wh[2], g_wl[2], acc);

#pragma unroll
    for (int i = 0; i < 4; i++) {
        const int m = m0 + wm + i * 16 + (lane >> 2);
#pragma unroll
        for (int j = 0; j < 8; j++) {
            const int n = n0 + wn + j * 8 + (lane & 3) * 2;
            const size_t o0 = (size_t)m * CD + n;
            const size_t o1 = (size_t)(m + 8) * CD + n;
            if (mode == 2) {
                *(float2*)(g_Sf + o0) = make_float2(acc[i][j][0], acc[i][j][1]);
                *(float2*)(g_Sf + o1) = make_float2(acc[i][j][2], acc[i][j][3]);
            } else if (mode == 0) {
                store_split2(g_Kh, g_Kl, o0, acc[i][j][0], acc[i][j][1]);
                store_split2(g_Kh, g_Kl, o1, acc[i][j][2], acc[i][j][3]);
            } else {
                *(__nv_bfloat162*)(g_Vb + o0) =
                    __floats2bfloat162_rn(acc[i][j][0], acc[i][j][1]);
                *(__nv_bfloat162*)(g_Vb + o1) =
                    __floats2bfloat162_rn(acc[i][j][2], acc[i][j][3]);
            }
        }
    }
}

// ---- final GEMM: (P+Sf) @ Wout^T -> out ------------------------------------
__global__ __launch_bounds__(128, 2) void gemm_out(float* __restrict__ Cout) {
    extern __shared__ __align__(128) char smem[];
    const uint32_t sb = smem_u32(smem);
    const int tid = threadIdx.x, wid = tid >> 5, lane = tid & 31;
    const int n0 = (int)blockIdx.x * 128;
    const int m0 = (int)blockIdx.y * 128;
    const int wm = (wid >> 1) * 64;
    const int wn = (wid & 1) * 64;

    float acc[4][8][4];
    gemm_core<true>(sb, tid, lane, wm, wn, m0, n0, g_xh, g_xl, g_wh[3], g_wl[3], acc);

#pragma unroll
    for (int i = 0; i < 4; i++) {
        const int m = m0 + wm + i * 16 + (lane >> 2);
#pragma unroll
        for (int j = 0; j < 8; j++) {
            const int n = n0 + wn + j * 8 + (lane & 3) * 2;
            *(float2*)(Cout + (size_t)m * CD + n) = make_float2(acc[i][j][0], acc[i][j][1]);
            *(float2*)(Cout + (size_t)(m + 8) * CD + n) = make_float2(acc[i][j][2], acc[i][j][3]);
        }
    }
}

// ============================================================================
// FA2-style causal attention on HMMA (Q == K). Q fragments hoisted; the dead
// Q smem buffers become the alternate K hi/lo buffers, so K(kb+1) and V(kb+1)
// loads fully overlap compute (double-buffered K, early-issued V).
// Epilogue fused: (P_norm + Sf) split -> g_xh/g_xl.
// ============================================================================
constexpr int A_RS = 272;
constexpr int A_TILE = 64 * A_RS;
constexpr int A_SMEM = 5 * A_TILE;

__global__ __launch_bounds__(128, 2) void fattn() {
    extern __shared__ __align__(128) char smem[];
    const uint32_t sb = smem_u32(smem);
    // buf0: KH0/KL0, buf1 (ex-Q): KH1/KL1, V single
    const uint32_t KH[2] = {2 * A_TILE, 0};
    const uint32_t KL[2] = {3 * A_TILE, A_TILE};
    const uint32_t SVB = 4 * A_TILE;

    const int qb = (int)(gridDim.x - 1 - blockIdx.x);  // heaviest first
    const int bh = blockIdx.y;
    const int b = bh >> 3, h = bh & 7;
    const int q0 = qb * 64;

    const int tid = threadIdx.x, wid = tid >> 5, lane = tid & 31;

    const __nv_bfloat16* Khg = g_Kh + (size_t)b * CS * CD + h * CHD;
    const __nv_bfloat16* Klg = g_Kl + (size_t)b * CS * CD + h * CHD;
    const __nv_bfloat16* Vbg = g_Vb + (size_t)b * CS * CD + h * CHD;

    // group 0: Q tiles (into buf1 slots)
    for (int t = tid; t < 64 * 16; t += 128) {
        int row = t >> 4, g = t & 15;
        uint32_t so = (uint32_t)(row * A_RS + g * 16);
        cp16(sb + KH[1] + so, Khg + (size_t)(q0 + row) * CD + g * 8);
        cp16(sb + KL[1] + so, Klg + (size_t)(q0 + row) * CD + g * 8);
    }
    CP_COMMIT();
    // group 1: K(0) into buf0
    for (int t = tid; t < 64 * 16; t += 128) {
        int row = t >> 4, g = t & 15;
        uint32_t so = (uint32_t)(row * A_RS + g * 16);
        cp16(sb + KH[0] + so, Khg + (size_t)row * CD + g * 8);
        cp16(sb + KL[0] + so, Klg + (size_t)row * CD + g * 8);
    }
    CP_COMMIT();
    // group 2: V(0)
    for (int t = tid; t < 64 * 16; t += 128) {
        int row = t >> 4, g = t & 15;
        cp16(sb + SVB + (uint32_t)(row * A_RS + g * 16), Vbg + (size_t)row * CD + g * 8);
    }
    CP_COMMIT();

    CP_WAIT2();          // Q ready
    __syncthreads();

    // hoist Q fragments (hi/lo) for all 8 k16 steps into registers
    uint32_t qhr[8][4], qlr[8][4];
#pragma unroll
    for (int ks = 0; ks < 8; ks++) {
        uint32_t qoff = (uint32_t)((wid * 16 + (lane & 15)) * A_RS + ks * 32 +
                                   (lane >> 4) * 16);
        ldsm4(qhr[ks], sb + KH[1] + qoff);
        ldsm4(qlr[ks], sb + KL[1] + qoff);
    }
    __syncthreads();     // buf1 free for K(1)

    float o[16][4];
#pragma unroll
    for (int t = 0; t < 16; t++)
#pragma unroll
        for (int r = 0; r < 4; r++) o[t][r] = 0.f;
    float m0r = -1e30f, m1r = -1e30f, l0 = 0.f, l1 = 0.f;
    const float scale = 0.08838834764831845f;  // 1/sqrt(128)

    for (int kb = 0; kb <= qb; kb++) {
        // issue K(next) into the other buffer (clamped dup on last iter)
        {
            const int kn0 = (kb < qb ? kb + 1 : qb) * 64;
            const uint32_t kh = KH[(kb + 1) & 1], kl = KL[(kb + 1) & 1];
            for (int t = tid; t < 64 * 16; t += 128) {
                int row = t >> 4, g = t & 15;
                uint32_t so = (uint32_t)(row * A_RS + g * 16);
                cp16(sb + kh + so, Khg + (size_t)(kn0 + row) * CD + g * 8);
                cp16(sb + kl + so, Klg + (size_t)(kn0 + row) * CD + g * 8);
            }
            CP_COMMIT();
        }
        CP_WAIT2();      // K(kb) ready (outstanding: V(kb), K(kb+1))
        __syncthreads();

        const uint32_t skh = KH[kb & 1], skl = KL[kb & 1];
        float s[8][4];
#pragma unroll
        for (int j = 0; j < 8; j++)
#pragma unroll
            for (int r = 0; r < 4; r++) s[j][r] = 0.f;

#pragma unroll
        for (int ks = 0; ks < 8; ks++) {
            uint32_t khf[16], klf[16];
#pragma unroll
            for (int j4 = 0; j4 < 4; j4++) {
                uint32_t koff = (uint32_t)((j4 * 16 + (lane & 15)) * A_RS + ks * 32 +
                                           (lane >> 4) * 16);
                ldsm4(khf + j4 * 4, sb + skh + koff);
                ldsm4(klf + j4 * 4, sb + skl + koff);
            }
#pragma unroll
            for (int j = 0; j < 8; j++) {
                uint32_t b2[2] = {khf[(j >> 1) * 4 + (j & 1)], khf[(j >> 1) * 4 + 2 + (j & 1)]};
                mma16816(s[j], qhr[ks], b2);
            }
#pragma unroll
            for (int j = 0; j < 8; j++) {
                uint32_t b2[2] = {klf[(j >> 1) * 4 + (j & 1)], klf[(j >> 1) * 4 + 2 + (j & 1)]};
                mma16816(s[j], qhr[ks], b2);
            }
#pragma unroll
            for (int j = 0; j < 8; j++) {
                uint32_t b2[2] = {khf[(j >> 1) * 4 + (j & 1)], khf[(j >> 1) * 4 + 2 + (j & 1)]};
                mma16816(s[j], qlr[ks], b2);
            }
        }

        const int r0l = wid * 16 + (lane >> 2);
#pragma unroll
        for (int j = 0; j < 8; j++) {
#pragma unroll
            for (int r = 0; r < 4; r++) s[j][r] = -s[j][r] * scale;
            if (kb == qb) {
                int cl = j * 8 + (lane & 3) * 2;
                if (cl > r0l) s[j][0] = -1e30f;
                if (cl + 1 > r0l) s[j][1] = -1e30f;
                if (cl > r0l + 8) s[j][2] = -1e30f;
                if (cl + 1 > r0l + 8) s[j][3] = -1e30f;
            }
        }

        float mx0 = -1e30f, mx1 = -1e30f;
#pragma unroll
        for (int j = 0; j < 8; j++) {
            mx0 = fmaxf(mx0, fmaxf(s[j][0], s[j][1]));
            mx1 = fmaxf(mx1, fmaxf(s[j][2], s[j][3]));
        }
        mx0 = fmaxf(mx0, __shfl_xor_sync(0xffffffffu, mx0, 1));
        mx0 = fmaxf(mx0, __shfl_xor_sync(0xffffffffu, mx0, 2));
        mx1 = fmaxf(mx1, __shfl_xor_sync(0xffffffffu, mx1, 1));
        mx1 = fmaxf(mx1, __shfl_xor_sync(0xffffffffu, mx1, 2));
        const float mn0 = fmaxf(m0r, mx0), mn1 = fmaxf(m1r, mx1);
        const float a0 = __expf(m0r - mn0), a1 = __expf(m1r - mn1);
        float sum0 = 0.f, sum1 = 0.f;
#pragma unroll
        for (int j = 0; j < 8; j++) {
            s[j][0] = __expf(s[j][0] - mn0);
            s[j][1] = __expf(s[j][1] - mn0);
            s[j][2] = __expf(s[j][2] - mn1);
            s[j][3] = __expf(s[j][3] - mn1);
            sum0 += s[j][0] + s[j][1];
            sum1 += s[j][2] + s[j][3];
        }
        sum0 += __shfl_xor_sync(0xffffffffu, sum0, 1);
        sum0 += __shfl_xor_sync(0xffffffffu, sum0, 2);
        sum1 += __shfl_xor_sync(0xffffffffu, sum1, 1);
        sum1 += __shfl_xor_sync(0xffffffffu, sum1, 2);
        l0 = l0 * a0 + sum0;
        l1 = l1 * a1 + sum1;
        m0r = mn0; m1r = mn1;
#pragma unroll
        for (int t = 0; t < 16; t++) {
            o[t][0] *= a0; o[t][1] *= a0; o[t][2] *= a1; o[t][3] *= a1;
        }

        CP_WAIT1();      // V(kb) ready (K(kb+1) still in flight)
        __syncthreads();

#pragma unroll
        for (int kg = 0; kg < 4; kg++) {
            uint32_t pa[4];
            {
                __nv_bfloat162 t0 = __floats2bfloat162_rn(s[2 * kg][0], s[2 * kg][1]);
                __nv_bfloat162 t1 = __floats2bfloat162_rn(s[2 * kg][2], s[2 * kg][3]);
                __nv_bfloat162 t2 = __floats2bfloat162_rn(s[2 * kg + 1][0], s[2 * kg + 1][1]);
                __nv_bfloat162 t3 = __floats2bfloat162_rn(s[2 * kg + 1][2], s[2 * kg + 1][3]);
                pa[0] = *(uint32_t*)&t0; pa[1] = *(uint32_t*)&t1;
                pa[2] = *(uint32_t*)&t2; pa[3] = *(uint32_t*)&t3;
            }
#pragma unroll
            for (int n2 = 0; n2 < 8; n2++) {
                uint32_t voff = (uint32_t)((kg * 16 + (lane & 15)) * A_RS + n2 * 32 +
                                           (lane >> 4) * 16);
                uint32_t vf[4];
                ldsm4t(vf, sb + SVB + voff);
                uint32_t b0[2] = {vf[0], vf[1]};
                uint32_t b1[2] = {vf[2], vf[3]};
                mma16816(o[2 * n2], pa, b0);
                mma16816(o[2 * n2 + 1], pa, b1);
            }
        }
        __syncthreads();  // all warps done reading V before refill

        // issue V(next) (clamped dup on last iter)
        {
            const int kn0 = (kb < qb ? kb + 1 : qb) * 64;
            for (int t = tid; t < 64 * 16; t += 128) {
                int row = t >> 4, g = t & 15;
                cp16(sb + SVB + (uint32_t)(row * A_RS + g * 16),
                     Vbg + (size_t)(kn0 + row) * CD + g * 8);
            }
            CP_COMMIT();
        }
    }

    // ---- fused epilogue: (P_norm + Sf) -> split -> g_xh/g_xl ----------------
    const float inv0 = 1.f / l0, inv1 = 1.f / l1;
    const size_t row0 = (size_t)(b * CS + q0 + wid * 16 + (lane >> 2));
#pragma unroll
    for (int t = 0; t < 16; t++) {
        const int col = h * CHD + t * 8 + (lane & 3) * 2;
        const size_t o0 = row0 * CD + col;
        const size_t o1 = (row0 + 8) * CD + col;
        float2 sf0 = *(const float2*)(g_Sf + o0);
        float2 sf1 = *(const float2*)(g_Sf + o1);
        store_split2(g_xh, g_xl, o0, o[t][0] * inv0 + sf0.x, o[t][1] * inv0 + sf0.y);
        store_split2(g_xh, g_xl, o1, o[t][2] * inv1 + sf1.x, o[t][3] * inv1 + sf1.y);
    }
}

// ============================================================================
// launch
// ============================================================================
extern "C" void kernel_launch(void* const* d_in, const int* in_sizes, int n_in,
                              void* d_out, int out_size) {
    const float* x  = (const float*)d_in[0];
    const float* Wk = (const float*)d_in[1];
    const float* Wv = (const float*)d_in[2];
    const float* Ws = (const float*)d_in[3];
    const float* Wo = (const float*)d_in[4];
    float* out = (float*)d_out;

    cudaFuncSetAttribute(gemm3, cudaFuncAttributeMaxDynamicSharedMemorySize, G_SMEM);
    cudaFuncSetAttribute(gemm_out, cudaFuncAttributeMaxDynamicSharedMemorySize, G_SMEM);
    cudaFuncSetAttribute(fattn, cudaFuncAttributeMaxDynamicSharedMemorySize, A_SMEM);

    const int PB = (int)((XQ + 4 * WQ) / 256);
    prep<<<PB, 256>>>(x, Wk, Wv, Ws, Wo);

    gemm3<<<dim3(24, CM / 128), 128, G_SMEM>>>();     // -> g_Kh/g_Kl, g_Vb, g_Sf

    fattn<<<dim3(CS / 64, CB * CH), 128, A_SMEM>>>(); // -> g_xh/g_xl (=P+Sf split)

    gemm_out<<<dim3(CD / 128, CM / 128), 128, G_SMEM>>>(out);
}

// round 11
// speedup vs baseline: 1.3015x; 1.3015x over previous
#include <cuda_runtime.h>
#include <cuda_fp16.h>
#include <cstdint>
#include <math.h>

// ---------------- problem constants ----------------
constexpr int CB = 2;        // batch
constexpr int CS = 2048;     // seq
constexpr int CD = 1024;     // model dim
constexpr int CH = 8;        // heads
constexpr int CHD = 128;     // head dim
constexpr int CM = CB * CS;  // 4096 rows

// ---------------- scratch (device globals; no allocations allowed) ----------
__device__ float g_Sf[CB * CS * CD];  // self_force = x @ Wself^T (fp32)

__device__ __half g_xh[CM * CD];      // A hi (x, later P+Sf)
__device__ __half g_xl[CM * CD];      // A lo
__device__ __half g_wh[4][CD * CD];   // W hi (k,v,self,out)
__device__ __half g_wl[4][CD * CD];   // W lo (used for self,out)

__device__ __half g_Kf[CB * CS * CD]; // K projection, fp16
__device__ __half g_Vf[CB * CS * CD]; // V projection, fp16

// ============================================================================
// PTX helpers (family-common sm_80+ only; tcgen05 unavailable on this ptxas)
// ============================================================================
__device__ __forceinline__ uint32_t smem_u32(const void* p) {
    uint32_t a;
    asm("{ .reg .u64 t; cvta.to.shared.u64 t, %1; cvt.u32.u64 %0, t; }" : "=r"(a) : "l"(p));
    return a;
}
__device__ __forceinline__ void cp16(uint32_t dst, const void* src) {
    asm volatile("cp.async.cg.shared.global [%0], [%1], 16;" :: "r"(dst), "l"(src) : "memory");
}
#define CP_COMMIT() asm volatile("cp.async.commit_group;" ::: "memory")
#define CP_WAIT0()  asm volatile("cp.async.wait_group 0;" ::: "memory")
#define CP_WAIT1()  asm volatile("cp.async.wait_group 1;" ::: "memory")

__device__ __forceinline__ void ldsm4(uint32_t* r, uint32_t addr) {
    asm volatile("ldmatrix.sync.aligned.m8n8.x4.shared.b16 {%0,%1,%2,%3}, [%4];"
                 : "=r"(r[0]), "=r"(r[1]), "=r"(r[2]), "=r"(r[3]) : "r"(addr));
}
__device__ __forceinline__ void ldsm4t(uint32_t* r, uint32_t addr) {
    asm volatile("ldmatrix.sync.aligned.m8n8.x4.trans.shared.b16 {%0,%1,%2,%3}, [%4];"
                 : "=r"(r[0]), "=r"(r[1]), "=r"(r[2]), "=r"(r[3]) : "r"(addr));
}
__device__ __forceinline__ void mma16816(float* d, const uint32_t* a, const uint32_t* b) {
    asm volatile(
        "mma.sync.aligned.m16n8k16.row.col.f32.f16.f16.f32 "
        "{%0,%1,%2,%3}, {%4,%5,%6,%7}, {%8,%9}, {%0,%1,%2,%3};\n"
        : "+f"(d[0]), "+f"(d[1]), "+f"(d[2]), "+f"(d[3])
        : "r"(a[0]), "r"(a[1]), "r"(a[2]), "r"(a[3]), "r"(b[0]), "r"(b[1]));
}

// ---- fp32 -> fp16 hi/lo helpers --------------------------------------------
__device__ __forceinline__ void split4(float4 v, __half2* hi2, __half2* lo2, size_t i2) {
    __half h0 = __float2half_rn(v.x), h1 = __float2half_rn(v.y);
    __half h2 = __float2half_rn(v.z), h3 = __float2half_rn(v.w);
    __half l0 = __float2half_rn(v.x - __half2float(h0));
    __half l1 = __float2half_rn(v.y - __half2float(h1));
    __half l2 = __float2half_rn(v.z - __half2float(h2));
    __half l3 = __float2half_rn(v.w - __half2float(h3));
    hi2[i2]     = __half2(h0, h1);
    hi2[i2 + 1] = __half2(h2, h3);
    lo2[i2]     = __half2(l0, l1);
    lo2[i2 + 1] = __half2(l2, l3);
}
__device__ __forceinline__ void store_split2(__half* H, __half* L, size_t off,
                                             float a, float b) {
    __half h0 = __float2half_rn(a), h1 = __float2half_rn(b);
    __half l0 = __float2half_rn(a - __half2float(h0));
    __half l1 = __float2half_rn(b - __half2float(h1));
    *(__half2*)(H + off) = __half2(h0, h1);
    *(__half2*)(L + off) = __half2(l0, l1);
}

// ============================================================================
// prep: one kernel splitting x and all 4 weights into fp16 hi/lo
// ============================================================================
constexpr size_t XQ = (size_t)CM * CD / 4;
constexpr size_t WQ = (size_t)CD * CD / 4;
__global__ __launch_bounds__(256) void prep(const float* __restrict__ x,
                                            const float* __restrict__ Wk,
                                            const float* __restrict__ Wv,
                                            const float* __restrict__ Ws,
                                            const float* __restrict__ Wo) {
    size_t i = (size_t)blockIdx.x * 256 + threadIdx.x;
    if (i < XQ) {
        split4(((const float4*)x)[i], (__half2*)g_xh, (__half2*)g_xl, i * 2);
    } else {
        size_t j = i - XQ;
        int w = (int)(j / WQ);
        size_t o = j % WQ;
        const float* W = (w == 0) ? Wk : (w == 1) ? Wv : (w == 2) ? Ws : Wo;
        split4(((const float4*)W)[o], (__half2*)g_wh[w], (__half2*)g_wl[w], o * 2);
    }
}

// ============================================================================
// HMMA fp16 GEMM core (R9 structure: K-chunk 32, 2-stage, proven best):
//   C = A @ W^T, 128x128 CTA tile, 4 warps of 64x64.
// NT=3: Ah*Bh + Ah*Bl + Al*Bh (fp16 split; err ~1e-5)
// NT=1: Ah*Bh plain fp16 (err ~1e-4)
// ============================================================================
constexpr int RSTRIDE = 80;
constexpr int TILE_B = 128 * RSTRIDE;
constexpr int STAGE_B = 4 * TILE_B;
constexpr int G_SMEM = 2 * STAGE_B;

template <int NT>
__device__ __forceinline__ void g_load(uint32_t st_, int m0, int n0, int k0, int tid,
                                       const __half* Ah_, const __half* Al_,
                                       const __half* Bh_, const __half* Bl_) {
    const int lr = tid >> 2;      // 0..31
    const int lc = tid & 3;       // 0..3 (16B segment)
#pragma unroll
    for (int rr = 0; rr < 4; rr++) {
        const int row = lr + rr * 32;
        const uint32_t so = (uint32_t)(row * RSTRIDE + lc * 16);
        const size_t gA = (size_t)(m0 + row) * CD + k0 + lc * 8;
        const size_t gB = (size_t)(n0 + row) * CD + k0 + lc * 8;
        cp16(st_ + 0 * TILE_B + so, Ah_ + gA);
        cp16(st_ + 2 * TILE_B + so, Bh_ + gB);
        if (NT == 3) {
            cp16(st_ + 1 * TILE_B + so, Al_ + gA);
            cp16(st_ + 3 * TILE_B + so, Bl_ + gB);
        }
    }
    CP_COMMIT();
}

template <int NT>
__device__ __forceinline__ void gemm_core(uint32_t sb, int tid, int lane, int wm, int wn,
                                          int m0, int n0,
                                          const __half* Ah_, const __half* Al_,
                                          const __half* Bh_, const __half* Bl_,
                                          float acc[4][8][4]) {
#pragma unroll
    for (int i = 0; i < 4; i++)
#pragma unroll
        for (int j = 0; j < 8; j++)
#pragma unroll
            for (int r = 0; r < 4; r++) acc[i][j][r] = 0.f;

    g_load<NT>(sb, m0, n0, 0, tid, Ah_, Al_, Bh_, Bl_);

    constexpr int NC = CD / 32;
    for (int c = 0; c < NC; c++) {
        if (c + 1 < NC) {
            g_load<NT>(sb + ((c + 1) & 1) * STAGE_B, m0, n0, (c + 1) * 32, tid,
                       Ah_, Al_, Bh_, Bl_);
            CP_WAIT1();
        } else {
            CP_WAIT0();
        }
        __syncthreads();

        const uint32_t st = sb + (c & 1) * STAGE_B;
#pragma unroll
        for (int h = 0; h < 2; h++) {
            uint32_t bh[16], bl[16];
#pragma unroll
            for (int j4 = 0; j4 < 4; j4++) {
                uint32_t off = (uint32_t)((wn + j4 * 16 + (lane & 15)) * RSTRIDE +
                                          (h * 2 + (lane >> 4)) * 16);
                ldsm4(bh + j4 * 4, st + 2 * TILE_B + off);
                if (NT == 3) ldsm4(bl + j4 * 4, st + 3 * TILE_B + off);
            }
#pragma unroll
            for (int i = 0; i < 4; i++) {
                uint32_t aoff = (uint32_t)((wm + i * 16 + (lane & 15)) * RSTRIDE +
                                           (h * 2 + (lane >> 4)) * 16);
                uint32_t ah[4], al[4];
                ldsm4(ah, st + 0 * TILE_B + aoff);
                if (NT == 3) ldsm4(al, st + 1 * TILE_B + aoff);
#pragma unroll
                for (int j = 0; j < 8; j++) {
                    uint32_t b2[2] = {bh[(j >> 1) * 4 + (j & 1)], bh[(j >> 1) * 4 + 2 + (j & 1)]};
                    mma16816(acc[i][j], ah, b2);
                }
                if (NT == 3) {
#pragma unroll
                    for (int j = 0; j < 8; j++) {
                        uint32_t b2[2] = {bl[(j >> 1) * 4 + (j & 1)],
                                          bl[(j >> 1) * 4 + 2 + (j & 1)]};
                        mma16816(acc[i][j], ah, b2);
                    }
#pragma unroll
                    for (int j = 0; j < 8; j++) {
                        uint32_t b2[2] = {bh[(j >> 1) * 4 + (j & 1)],
                                          bh[(j >> 1) * 4 + 2 + (j & 1)]};
                        mma16816(acc[i][j], al, b2);
                    }
                }
            }
        }
        __syncthreads();
    }
}

// ---- the 3 projection GEMMs in one launch ----------------------------------
// heavy-first block order: bx 0-7 -> Sf (3-term), 8-15 -> K (1-term), 16-23 -> V
__global__ __launch_bounds__(128, 2) void gemm3() {
    extern __shared__ __align__(128) char smem[];
    const uint32_t sb = smem_u32(smem);
    const int tid = threadIdx.x, wid = tid >> 5, lane = tid & 31;
    const int mraw = (int)(blockIdx.x >> 3);
    const int mode = (mraw == 0) ? 2 : (mraw - 1);    // 2=Sf first, then 0=K, 1=V
    const int n0 = (int)(blockIdx.x & 7) * 128;
    const int m0 = (int)blockIdx.y * 128;
    const int wm = (wid >> 1) * 64;
    const int wn = (wid & 1) * 64;

    float acc[4][8][4];
    if (mode == 2)
        gemm_core<3>(sb, tid, lane, wm, wn, m0, n0, g_xh, g_xl, g_wh[2], g_wl[2], acc);
    else if (mode == 0)
        gemm_core<1>(sb, tid, lane, wm, wn, m0, n0, g_xh, g_xl, g_wh[0], g_wl[0], acc);
    else
        gemm_core<1>(sb, tid, lane, wm, wn, m0, n0, g_xh, g_xl, g_wh[1], g_wl[1], acc);

#pragma unroll
    for (int i = 0; i < 4; i++) {
        const int m = m0 + wm + i * 16 + (lane >> 2);
#pragma unroll
        for (int j = 0; j < 8; j++) {
            const int n = n0 + wn + j * 8 + (lane & 3) * 2;
            const size_t o0 = (size_t)m * CD + n;
            const size_t o1 = (size_t)(m + 8) * CD + n;
            if (mode == 2) {
                *(float2*)(g_Sf + o0) = make_float2(acc[i][j][0], acc[i][j][1]);
                *(float2*)(g_Sf + o1) = make_float2(acc[i][j][2], acc[i][j][3]);
            } else {
                __half* dst = (mode == 0) ? g_Kf : g_Vf;
                *(__half2*)(dst + o0) = __floats2half2_rn(acc[i][j][0], acc[i][j][1]);
                *(__half2*)(dst + o1) = __floats2half2_rn(acc[i][j][2], acc[i][j][3]);
            }
        }
    }
}

// ---- final GEMM: (P+Sf) @ Wout^T -> out (3-term fp16) -----------------------
__global__ __launch_bounds__(128, 2) void gemm_out(float* __restrict__ Cout) {
    extern __shared__ __align__(128) char smem[];
    const uint32_t sb = smem_u32(smem);
    const int tid = threadIdx.x, wid = tid >> 5, lane = tid & 31;
    const int n0 = (int)blockIdx.x * 128;
    const int m0 = (int)blockIdx.y * 128;
    const int wm = (wid >> 1) * 64;
    const int wn = (wid & 1) * 64;

    float acc[4][8][4];
    gemm_core<3>(sb, tid, lane, wm, wn, m0, n0, g_xh, g_xl, g_wh[3], g_wl[3], acc);

#pragma unroll
    for (int i = 0; i < 4; i++) {
        const int m = m0 + wm + i * 16 + (lane >> 2);
#pragma unroll
        for (int j = 0; j < 8; j++) {
            const int n = n0 + wn + j * 8 + (lane & 3) * 2;
            *(float2*)(Cout + (size_t)m * CD + n) = make_float2(acc[i][j][0], acc[i][j][1]);
            *(float2*)(Cout + (size_t)(m + 8) * CD + n) = make_float2(acc[i][j][2], acc[i][j][3]);
        }
    }
}

// ============================================================================
// FA2-style causal attention on HMMA (Q == K), 1-term fp16 scores + fp16 P@V.
// Q fragments hoisted. Epilogue fused: (P_norm + Sf) split -> g_xh/g_xl.
// ============================================================================
constexpr int A_RS = 272;             // 128 fp16 = 256 B + 16 pad
constexpr int A_TILE = 64 * A_RS;
constexpr int A_SMEM = 3 * A_TILE;    // Q, K, V

__global__ __launch_bounds__(128, 2) void fattn() {
    extern __shared__ __align__(128) char smem[];
    const uint32_t sb = smem_u32(smem);
    const uint32_t SQ = 0, SK = A_TILE, SV = 2 * A_TILE;

    const int qb = (int)(gridDim.x - 1 - blockIdx.x);  // heaviest first
    const int bh = blockIdx.y;
    const int b = bh >> 3, h = bh & 7;
    const int q0 = qb * 64;

    const int tid = threadIdx.x, wid = tid >> 5, lane = tid & 31;

    const __half* Kg = g_Kf + (size_t)b * CS * CD + h * CHD;
    const __half* Vg = g_Vf + (size_t)b * CS * CD + h * CHD;

    // load Q tile (rows q0..q0+63 of K)
    for (int t = tid; t < 64 * 16; t += 128) {
        int row = t >> 4, g = t & 15;
        cp16(sb + SQ + (uint32_t)(row * A_RS + g * 16),
             Kg + (size_t)(q0 + row) * CD + g * 8);
    }
    CP_COMMIT();
    CP_WAIT0();
    __syncthreads();

    // hoist Q fragments for all 8 k16 steps into registers
    uint32_t qf[8][4];
#pragma unroll
    for (int ks = 0; ks < 8; ks++) {
        uint32_t qoff = (uint32_t)((wid * 16 + (lane & 15)) * A_RS + ks * 32 +
                                   (lane >> 4) * 16);
        ldsm4(qf[ks], sb + SQ + qoff);
    }

    float o[16][4];
#pragma unroll
    for (int t = 0; t < 16; t++)
#pragma unroll
        for (int r = 0; r < 4; r++) o[t][r] = 0.f;
    float m0r = -1e30f, m1r = -1e30f, l0 = 0.f, l1 = 0.f;
    const float scale = 0.08838834764831845f;  // 1/sqrt(128)

    for (int kb = 0; kb <= qb; kb++) {
        const int k0 = kb * 64;
        __syncthreads();
        for (int t = tid; t < 64 * 16; t += 128) {
            int row = t >> 4, g = t & 15;
            uint32_t so = (uint32_t)(row * A_RS + g * 16);
            cp16(sb + SK + so, Kg + (size_t)(k0 + row) * CD + g * 8);
            cp16(sb + SV + so, Vg + (size_t)(k0 + row) * CD + g * 8);
        }
        CP_COMMIT();
        CP_WAIT0();
        __syncthreads();

        float s[8][4];
#pragma unroll
        for (int j = 0; j < 8; j++)
#pragma unroll
            for (int r = 0; r < 4; r++) s[j][r] = 0.f;

#pragma unroll
        for (int ks = 0; ks < 8; ks++) {
            uint32_t kf[16];
#pragma unroll
            for (int j4 = 0; j4 < 4; j4++) {
                uint32_t koff = (uint32_t)((j4 * 16 + (lane & 15)) * A_RS + ks * 32 +
                                           (lane >> 4) * 16);
                ldsm4(kf + j4 * 4, sb + SK + koff);
            }
#pragma unroll
            for (int j = 0; j < 8; j++) {
                uint32_t b2[2] = {kf[(j >> 1) * 4 + (j & 1)], kf[(j >> 1) * 4 + 2 + (j & 1)]};
                mma16816(s[j], qf[ks], b2);
            }
        }

        const int r0l = wid * 16 + (lane >> 2);
#pragma unroll
        for (int j = 0; j < 8; j++) {
#pragma unroll
            for (int r = 0; r < 4; r++) s[j][r] = -s[j][r] * scale;
            if (kb == qb) {
                int cl = j * 8 + (lane & 3) * 2;
                if (cl > r0l) s[j][0] = -1e30f;
                if (cl + 1 > r0l) s[j][1] = -1e30f;
                if (cl > r0l + 8) s[j][2] = -1e30f;
                if (cl + 1 > r0l + 8) s[j][3] = -1e30f;
            }
        }

        float mx0 = -1e30f, mx1 = -1e30f;
#pragma unroll
        for (int j = 0; j < 8; j++) {
            mx0 = fmaxf(mx0, fmaxf(s[j][0], s[j][1]));
            mx1 = fmaxf(mx1, fmaxf(s[j][2], s[j][3]));
        }
        mx0 = fmaxf(mx0, __shfl_xor_sync(0xffffffffu, mx0, 1));
        mx0 = fmaxf(mx0, __shfl_xor_sync(0xffffffffu, mx0, 2));
        mx1 = fmaxf(mx1, __shfl_xor_sync(0xffffffffu, mx1, 1));
        mx1 = fmaxf(mx1, __shfl_xor_sync(0xffffffffu, mx1, 2));
        const float mn0 = fmaxf(m0r, mx0), mn1 = fmaxf(m1r, mx1);
        const float a0 = __expf(m0r - mn0), a1 = __expf(m1r - mn1);
        float sum0 = 0.f, sum1 = 0.f;
#pragma unroll
        for (int j = 0; j < 8; j++) {
            s[j][0] = __expf(s[j][0] - mn0);
            s[j][1] = __expf(s[j][1] - mn0);
            s[j][2] = __expf(s[j][2] - mn1);
            s[j][3] = __expf(s[j][3] - mn1);
            sum0 += s[j][0] + s[j][1];
            sum1 += s[j][2] + s[j][3];
        }
        sum0 += __shfl_xor_sync(0xffffffffu, sum0, 1);
        sum0 += __shfl_xor_sync(0xffffffffu, sum0, 2);
        sum1 += __shfl_xor_sync(0xffffffffu, sum1, 1);
        sum1 += __shfl_xor_sync(0xffffffffu, sum1, 2);
        l0 = l0 * a0 + sum0;
        l1 = l1 * a1 + sum1;
        m0r = mn0; m1r = mn1;
#pragma unroll
        for (int t = 0; t < 16; t++) {
            o[t][0] *= a0; o[t][1] *= a0; o[t][2] *= a1; o[t][3] *= a1;
        }

#pragma unroll
        for (int kg = 0; kg < 4; kg++) {
            uint32_t pa[4];
            {
                __half2 t0 = __floats2half2_rn(s[2 * kg][0], s[2 * kg][1]);
                __half2 t1 = __floats2half2_rn(s[2 * kg][2], s[2 * kg][3]);
                __half2 t2 = __floats2half2_rn(s[2 * kg + 1][0], s[2 * kg + 1][1]);
                __half2 t3 = __floats2half2_rn(s[2 * kg + 1][2], s[2 * kg + 1][3]);
                pa[0] = *(uint32_t*)&t0; pa[1] = *(uint32_t*)&t1;
                pa[2] = *(uint32_t*)&t2; pa[3] = *(uint32_t*)&t3;
            }
#pragma unroll
            for (int n2 = 0; n2 < 8; n2++) {
                uint32_t voff = (uint32_t)((kg * 16 + (lane & 15)) * A_RS + n2 * 32 +
                                           (lane >> 4) * 16);
                uint32_t vf[4];
                ldsm4t(vf, sb + SV + voff);
                uint32_t b0[2] = {vf[0], vf[1]};
                uint32_t b1[2] = {vf[2], vf[3]};
                mma16816(o[2 * n2], pa, b0);
                mma16816(o[2 * n2 + 1], pa, b1);
            }
        }
    }

    // ---- fused epilogue: (P_norm + Sf) -> split -> g_xh/g_xl ----------------
    const float inv0 = 1.f / l0, inv1 = 1.f / l1;
    const size_t row0 = (size_t)(b * CS + q0 + wid * 16 + (lane >> 2));
#pragma unroll
    for (int t = 0; t < 16; t++) {
        const int col = h * CHD + t * 8 + (lane & 3) * 2;
        const size_t o0 = row0 * CD + col;
        const size_t o1 = (row0 + 8) * CD + col;
        float2 sf0 = *(const float2*)(g_Sf + o0);
        float2 sf1 = *(const float2*)(g_Sf + o1);
        store_split2(g_xh, g_xl, o0, o[t][0] * inv0 + sf0.x, o[t][1] * inv0 + sf0.y);
        store_split2(g_xh, g_xl, o1, o[t][2] * inv1 + sf1.x, o[t][3] * inv1 + sf1.y);
    }
}

// ============================================================================
// launch
// ============================================================================
extern "C" void kernel_launch(void* const* d_in, const int* in_sizes, int n_in,
                              void* d_out, int out_size) {
    const float* x  = (const float*)d_in[0];
    const float* Wk = (const float*)d_in[1];
    const float* Wv = (const float*)d_in[2];
    const float* Ws = (const float*)d_in[3];
    const float* Wo = (const float*)d_in[4];
    float* out = (float*)d_out;

    cudaFuncSetAttribute(gemm3, cudaFuncAttributeMaxDynamicSharedMemorySize, G_SMEM);
    cudaFuncSetAttribute(gemm_out, cudaFuncAttributeMaxDynamicSharedMemorySize, G_SMEM);
    cudaFuncSetAttribute(fattn, cudaFuncAttributeMaxDynamicSharedMemorySize, A_SMEM);

    const int PB = (int)((XQ + 4 * WQ) / 256);
    prep<<<PB, 256>>>(x, Wk, Wv, Ws, Wo);

    gemm3<<<dim3(24, CM / 128), 128, G_SMEM>>>();     // -> g_Kf, g_Vf, g_Sf

    fattn<<<dim3(CS / 64, CB * CH), 128, A_SMEM>>>(); // -> g_xh/g_xl (=P+Sf split)

    gemm_out<<<dim3(CD / 128, CM / 128), 128, G_SMEM>>>(out);
}

// round 12
// speedup vs baseline: 1.9538x; 1.5013x over previous
#include <cuda_runtime.h>
#include <cuda_fp16.h>
#include <cstdint>
#include <math.h>

// ---------------- problem constants ----------------
constexpr int CB = 2;        // batch
constexpr int CS = 2048;     // seq
constexpr int CD = 1024;     // model dim
constexpr int CH = 8;        // heads
constexpr int CHD = 128;     // head dim
constexpr int CM = CB * CS;  // 4096 rows

// ---------------- scratch (device globals; no allocations allowed) ----------
__device__ float g_Sf[CB * CS * CD];  // self_force = x @ Wself^T (fp32)

__device__ __half g_xf[CM * CD];      // A operand fp16 (x, later P+Sf)
__device__ __half g_wf[4][CD * CD];   // weights fp16 (k,v,self,out)

__device__ __half g_Kf[CB * CS * CD]; // K projection, fp16
__device__ __half g_Vf[CB * CS * CD]; // V projection, fp16

// ============================================================================
// PTX helpers (family-common sm_80+ only; tcgen05 unavailable on this ptxas)
// ============================================================================
__device__ __forceinline__ uint32_t smem_u32(const void* p) {
    uint32_t a;
    asm("{ .reg .u64 t; cvta.to.shared.u64 t, %1; cvt.u32.u64 %0, t; }" : "=r"(a) : "l"(p));
    return a;
}
__device__ __forceinline__ void cp16(uint32_t dst, const void* src) {
    asm volatile("cp.async.cg.shared.global [%0], [%1], 16;" :: "r"(dst), "l"(src) : "memory");
}
#define CP_COMMIT() asm volatile("cp.async.commit_group;" ::: "memory")
#define CP_WAIT0()  asm volatile("cp.async.wait_group 0;" ::: "memory")
#define CP_WAIT1()  asm volatile("cp.async.wait_group 1;" ::: "memory")

__device__ __forceinline__ void ldsm4(uint32_t* r, uint32_t addr) {
    asm volatile("ldmatrix.sync.aligned.m8n8.x4.shared.b16 {%0,%1,%2,%3}, [%4];"
                 : "=r"(r[0]), "=r"(r[1]), "=r"(r[2]), "=r"(r[3]) : "r"(addr));
}
__device__ __forceinline__ void ldsm4t(uint32_t* r, uint32_t addr) {
    asm volatile("ldmatrix.sync.aligned.m8n8.x4.trans.shared.b16 {%0,%1,%2,%3}, [%4];"
                 : "=r"(r[0]), "=r"(r[1]), "=r"(r[2]), "=r"(r[3]) : "r"(addr));
}
__device__ __forceinline__ void mma16816(float* d, const uint32_t* a, const uint32_t* b) {
    asm volatile(
        "mma.sync.aligned.m16n8k16.row.col.f32.f16.f16.f32 "
        "{%0,%1,%2,%3}, {%4,%5,%6,%7}, {%8,%9}, {%0,%1,%2,%3};\n"
        : "+f"(d[0]), "+f"(d[1]), "+f"(d[2]), "+f"(d[3])
        : "r"(a[0]), "r"(a[1]), "r"(a[2]), "r"(a[3]), "r"(b[0]), "r"(b[1]));
}

// ============================================================================
// prep: fp32 -> fp16 conversion of x and all 4 weights (no split needed)
// ============================================================================
constexpr size_t XQ = (size_t)CM * CD / 4;
constexpr size_t WQ = (size_t)CD * CD / 4;
__global__ __launch_bounds__(256) void prep(const float* __restrict__ x,
                                            const float* __restrict__ Wk,
                                            const float* __restrict__ Wv,
                                            const float* __restrict__ Ws,
                                            const float* __restrict__ Wo) {
    size_t i = (size_t)blockIdx.x * 256 + threadIdx.x;
    const float* src;
    __half2* dst;
    size_t o;
    if (i < XQ) {
        src = x; dst = (__half2*)g_xf; o = i;
    } else {
        size_t j = i - XQ;
        int w = (int)(j / WQ);
        o = j % WQ;
        src = (w == 0) ? Wk : (w == 1) ? Wv : (w == 2) ? Ws : Wo;
        dst = (__half2*)g_wf[w];
    }
    float4 v = ((const float4*)src)[o];
    dst[o * 2]     = __floats2half2_rn(v.x, v.y);
    dst[o * 2 + 1] = __floats2half2_rn(v.z, v.w);
}

// ============================================================================
// HMMA fp16 GEMM core (1-term):  C = A @ W^T, 128x128 CTA tile,
// 4 warps of 64x64, K-chunk 32, 2-stage cp.async double buffer.
// ============================================================================
constexpr int RSTRIDE = 80;
constexpr int TILE_B = 128 * RSTRIDE;
constexpr int STAGE_B = 2 * TILE_B;      // A, B tiles
constexpr int G_SMEM = 2 * STAGE_B;      // 40960 B

__device__ __forceinline__ void g_load(uint32_t st_, int m0, int n0, int k0, int tid,
                                       const __half* A_, const __half* B_) {
    const int lr = tid >> 2;      // 0..31
    const int lc = tid & 3;       // 0..3 (16B segment)
#pragma unroll
    for (int rr = 0; rr < 4; rr++) {
        const int row = lr + rr * 32;
        const uint32_t so = (uint32_t)(row * RSTRIDE + lc * 16);
        cp16(st_ + 0 * TILE_B + so, A_ + (size_t)(m0 + row) * CD + k0 + lc * 8);
        cp16(st_ + 1 * TILE_B + so, B_ + (size_t)(n0 + row) * CD + k0 + lc * 8);
    }
    CP_COMMIT();
}

__device__ __forceinline__ void gemm_core(uint32_t sb, int tid, int lane, int wm, int wn,
                                          int m0, int n0,
                                          const __half* A_, const __half* B_,
                                          float acc[4][8][4]) {
#pragma unroll
    for (int i = 0; i < 4; i++)
#pragma unroll
        for (int j = 0; j < 8; j++)
#pragma unroll
            for (int r = 0; r < 4; r++) acc[i][j][r] = 0.f;

    g_load(sb, m0, n0, 0, tid, A_, B_);

    constexpr int NC = CD / 32;
    for (int c = 0; c < NC; c++) {
        if (c + 1 < NC) {
            g_load(sb + ((c + 1) & 1) * STAGE_B, m0, n0, (c + 1) * 32, tid, A_, B_);
            CP_WAIT1();
        } else {
            CP_WAIT0();
        }
        __syncthreads();

        const uint32_t st = sb + (c & 1) * STAGE_B;
#pragma unroll
        for (int h = 0; h < 2; h++) {
            uint32_t bf[16];
#pragma unroll
            for (int j4 = 0; j4 < 4; j4++) {
                uint32_t off = (uint32_t)((wn + j4 * 16 + (lane & 15)) * RSTRIDE +
                                          (h * 2 + (lane >> 4)) * 16);
                ldsm4(bf + j4 * 4, st + 1 * TILE_B + off);
            }
#pragma unroll
            for (int i = 0; i < 4; i++) {
                uint32_t aoff = (uint32_t)((wm + i * 16 + (lane & 15)) * RSTRIDE +
                                           (h * 2 + (lane >> 4)) * 16);
                uint32_t af[4];
                ldsm4(af, st + 0 * TILE_B + aoff);
#pragma unroll
                for (int j = 0; j < 8; j++) {
                    uint32_t b2[2] = {bf[(j >> 1) * 4 + (j & 1)], bf[(j >> 1) * 4 + 2 + (j & 1)]};
                    mma16816(acc[i][j], af, b2);
                }
            }
        }
        __syncthreads();
    }
}

// ---- the 3 projection GEMMs in one launch ----------------------------------
__global__ __launch_bounds__(128, 2) void gemm3() {
    extern __shared__ __align__(128) char smem[];
    const uint32_t sb = smem_u32(smem);
    const int tid = threadIdx.x, wid = tid >> 5, lane = tid & 31;
    const int mode = (int)(blockIdx.x >> 3);          // 0=K 1=V 2=Sf
    const int n0 = (int)(blockIdx.x & 7) * 128;
    const int m0 = (int)blockIdx.y * 128;
    const int wm = (wid >> 1) * 64;
    const int wn = (wid & 1) * 64;

    float acc[4][8][4];
    gemm_core(sb, tid, lane, wm, wn, m0, n0, g_xf, g_wf[mode], acc);

#pragma unroll
    for (int i = 0; i < 4; i++) {
        const int m = m0 + wm + i * 16 + (lane >> 2);
#pragma unroll
        for (int j = 0; j < 8; j++) {
            const int n = n0 + wn + j * 8 + (lane & 3) * 2;
            const size_t o0 = (size_t)m * CD + n;
            const size_t o1 = (size_t)(m + 8) * CD + n;
            if (mode == 2) {
                *(float2*)(g_Sf + o0) = make_float2(acc[i][j][0], acc[i][j][1]);
                *(float2*)(g_Sf + o1) = make_float2(acc[i][j][2], acc[i][j][3]);
            } else {
                __half* dst = (mode == 0) ? g_Kf : g_Vf;
                *(__half2*)(dst + o0) = __floats2half2_rn(acc[i][j][0], acc[i][j][1]);
                *(__half2*)(dst + o1) = __floats2half2_rn(acc[i][j][2], acc[i][j][3]);
            }
        }
    }
}

// ---- final GEMM: (P+Sf) @ Wout^T -> out -------------------------------------
__global__ __launch_bounds__(128, 2) void gemm_out(float* __restrict__ Cout) {
    extern __shared__ __align__(128) char smem[];
    const uint32_t sb = smem_u32(smem);
    const int tid = threadIdx.x, wid = tid >> 5, lane = tid & 31;
    const int n0 = (int)blockIdx.x * 128;
    const int m0 = (int)blockIdx.y * 128;
    const int wm = (wid >> 1) * 64;
    const int wn = (wid & 1) * 64;

    float acc[4][8][4];
    gemm_core(sb, tid, lane, wm, wn, m0, n0, g_xf, g_wf[3], acc);

#pragma unroll
    for (int i = 0; i < 4; i++) {
        const int m = m0 + wm + i * 16 + (lane >> 2);
#pragma unroll
        for (int j = 0; j < 8; j++) {
            const int n = n0 + wn + j * 8 + (lane & 3) * 2;
            *(float2*)(Cout + (size_t)m * CD + n) = make_float2(acc[i][j][0], acc[i][j][1]);
            *(float2*)(Cout + (size_t)(m + 8) * CD + n) = make_float2(acc[i][j][2], acc[i][j][3]);
        }
    }
}

// ============================================================================
// FA2-style causal attention on HMMA (Q == K), fp16 scores + fp16 P@V.
// Q fragments hoisted. Epilogue fused: (P_norm + Sf) -> fp16 -> g_xf.
// ============================================================================
constexpr int A_RS = 272;             // 128 fp16 = 256 B + 16 pad
constexpr int A_TILE = 64 * A_RS;
constexpr int A_SMEM = 3 * A_TILE;    // Q, K, V

__global__ __launch_bounds__(128, 2) void fattn() {
    extern __shared__ __align__(128) char smem[];
    const uint32_t sb = smem_u32(smem);
    const uint32_t SQ = 0, SK = A_TILE, SV = 2 * A_TILE;

    const int qb = (int)(gridDim.x - 1 - blockIdx.x);  // heaviest first
    const int bh = blockIdx.y;
    const int b = bh >> 3, h = bh & 7;
    const int q0 = qb * 64;

    const int tid = threadIdx.x, wid = tid >> 5, lane = tid & 31;

    const __half* Kg = g_Kf + (size_t)b * CS * CD + h * CHD;
    const __half* Vg = g_Vf + (size_t)b * CS * CD + h * CHD;

    // load Q tile (rows q0..q0+63 of K)
    for (int t = tid; t < 64 * 16; t += 128) {
        int row = t >> 4, g = t & 15;
        cp16(sb + SQ + (uint32_t)(row * A_RS + g * 16),
             Kg + (size_t)(q0 + row) * CD + g * 8);
    }
    CP_COMMIT();
    CP_WAIT0();
    __syncthreads();

    // hoist Q fragments for all 8 k16 steps into registers
    uint32_t qf[8][4];
#pragma unroll
    for (int ks = 0; ks < 8; ks++) {
        uint32_t qoff = (uint32_t)((wid * 16 + (lane & 15)) * A_RS + ks * 32 +
                                   (lane >> 4) * 16);
        ldsm4(qf[ks], sb + SQ + qoff);
    }

    float o[16][4];
#pragma unroll
    for (int t = 0; t < 16; t++)
#pragma unroll
        for (int r = 0; r < 4; r++) o[t][r] = 0.f;
    float m0r = -1e30f, m1r = -1e30f, l0 = 0.f, l1 = 0.f;
    const float scale = 0.08838834764831845f;  // 1/sqrt(128)

    for (int kb = 0; kb <= qb; kb++) {
        const int k0 = kb * 64;
        __syncthreads();
        for (int t = tid; t < 64 * 16; t += 128) {
            int row = t >> 4, g = t & 15;
            uint32_t so = (uint32_t)(row * A_RS + g * 16);
            cp16(sb + SK + so, Kg + (size_t)(k0 + row) * CD + g * 8);
            cp16(sb + SV + so, Vg + (size_t)(k0 + row) * CD + g * 8);
        }
        CP_COMMIT();
        CP_WAIT0();
        __syncthreads();

        float s[8][4];
#pragma unroll
        for (int j = 0; j < 8; j++)
#pragma unroll
            for (int r = 0; r < 4; r++) s[j][r] = 0.f;

#pragma unroll
        for (int ks = 0; ks < 8; ks++) {
            uint32_t kf[16];
#pragma unroll
            for (int j4 = 0; j4 < 4; j4++) {
                uint32_t koff = (uint32_t)((j4 * 16 + (lane & 15)) * A_RS + ks * 32 +
                                           (lane >> 4) * 16);
                ldsm4(kf + j4 * 4, sb + SK + koff);
            }
#pragma unroll
            for (int j = 0; j < 8; j++) {
                uint32_t b2[2] = {kf[(j >> 1) * 4 + (j & 1)], kf[(j >> 1) * 4 + 2 + (j & 1)]};
                mma16816(s[j], qf[ks], b2);
            }
        }

        const int r0l = wid * 16 + (lane >> 2);
#pragma unroll
        for (int j = 0; j < 8; j++) {
#pragma unroll
            for (int r = 0; r < 4; r++) s[j][r] = -s[j][r] * scale;
            if (kb == qb) {
                int cl = j * 8 + (lane & 3) * 2;
                if (cl > r0l) s[j][0] = -1e30f;
                if (cl + 1 > r0l) s[j][1] = -1e30f;
                if (cl > r0l + 8) s[j][2] = -1e30f;
                if (cl + 1 > r0l + 8) s[j][3] = -1e30f;
            }
        }

        float mx0 = -1e30f, mx1 = -1e30f;
#pragma unroll
        for (int j = 0; j < 8; j++) {
            mx0 = fmaxf(mx0, fmaxf(s[j][0], s[j][1]));
            mx1 = fmaxf(mx1, fmaxf(s[j][2], s[j][3]));
        }
        mx0 = fmaxf(mx0, __shfl_xor_sync(0xffffffffu, mx0, 1));
        mx0 = fmaxf(mx0, __shfl_xor_sync(0xffffffffu, mx0, 2));
        mx1 = fmaxf(mx1, __shfl_xor_sync(0xffffffffu, mx1, 1));
        mx1 = fmaxf(mx1, __shfl_xor_sync(0xffffffffu, mx1, 2));
        const float mn0 = fmaxf(m0r, mx0), mn1 = fmaxf(m1r, mx1);
        const float a0 = __expf(m0r - mn0), a1 = __expf(m1r - mn1);
        float sum0 = 0.f, sum1 = 0.f;
#pragma unroll
        for (int j = 0; j < 8; j++) {
            s[j][0] = __expf(s[j][0] - mn0);
            s[j][1] = __expf(s[j][1] - mn0);
            s[j][2] = __expf(s[j][2] - mn1);
            s[j][3] = __expf(s[j][3] - mn1);
            sum0 += s[j][0] + s[j][1];
            sum1 += s[j][2] + s[j][3];
        }
        sum0 += __shfl_xor_sync(0xffffffffu, sum0, 1);
        sum0 += __shfl_xor_sync(0xffffffffu, sum0, 2);
        sum1 += __shfl_xor_sync(0xffffffffu, sum1, 1);
        sum1 += __shfl_xor_sync(0xffffffffu, sum1, 2);
        l0 = l0 * a0 + sum0;
        l1 = l1 * a1 + sum1;
        m0r = mn0; m1r = mn1;
#pragma unroll
        for (int t = 0; t < 16; t++) {
            o[t][0] *= a0; o[t][1] *= a0; o[t][2] *= a1; o[t][3] *= a1;
        }

#pragma unroll
        for (int kg = 0; kg < 4; kg++) {
            uint32_t pa[4];
            {
                __half2 t0 = __floats2half2_rn(s[2 * kg][0], s[2 * kg][1]);
                __half2 t1 = __floats2half2_rn(s[2 * kg][2], s[2 * kg][3]);
                __half2 t2 = __floats2half2_rn(s[2 * kg + 1][0], s[2 * kg + 1][1]);
                __half2 t3 = __floats2half2_rn(s[2 * kg + 1][2], s[2 * kg + 1][3]);
                pa[0] = *(uint32_t*)&t0; pa[1] = *(uint32_t*)&t1;
                pa[2] = *(uint32_t*)&t2; pa[3] = *(uint32_t*)&t3;
            }
#pragma unroll
            for (int n2 = 0; n2 < 8; n2++) {
                uint32_t voff = (uint32_t)((kg * 16 + (lane & 15)) * A_RS + n2 * 32 +
                                           (lane >> 4) * 16);
                uint32_t vf[4];
                ldsm4t(vf, sb + SV + voff);
                uint32_t b0[2] = {vf[0], vf[1]};
                uint32_t b1[2] = {vf[2], vf[3]};
                mma16816(o[2 * n2], pa, b0);
                mma16816(o[2 * n2 + 1], pa, b1);
            }
        }
    }

    // ---- fused epilogue: (P_norm + Sf) -> fp16 -> g_xf ----------------------
    const float inv0 = 1.f / l0, inv1 = 1.f / l1;
    const size_t row0 = (size_t)(b * CS + q0 + wid * 16 + (lane >> 2));
#pragma unroll
    for (int t = 0; t < 16; t++) {
        const int col = h * CHD + t * 8 + (lane & 3) * 2;
        const size_t o0 = row0 * CD + col;
        const size_t o1 = (row0 + 8) * CD + col;
        float2 sf0 = *(const float2*)(g_Sf + o0);
        float2 sf1 = *(const float2*)(g_Sf + o1);
        *(__half2*)(g_xf + o0) =
            __floats2half2_rn(o[t][0] * inv0 + sf0.x, o[t][1] * inv0 + sf0.y);
        *(__half2*)(g_xf + o1) =
            __floats2half2_rn(o[t][2] * inv1 + sf1.x, o[t][3] * inv1 + sf1.y);
    }
}

// ============================================================================
// launch
// ============================================================================
extern "C" void kernel_launch(void* const* d_in, const int* in_sizes, int n_in,
                              void* d_out, int out_size) {
    const float* x  = (const float*)d_in[0];
    const float* Wk = (const float*)d_in[1];
    const float* Wv = (const float*)d_in[2];
    const float* Ws = (const float*)d_in[3];
    const float* Wo = (const float*)d_in[4];
    float* out = (float*)d_out;

    cudaFuncSetAttribute(gemm3, cudaFuncAttributeMaxDynamicSharedMemorySize, G_SMEM);
    cudaFuncSetAttribute(gemm_out, cudaFuncAttributeMaxDynamicSharedMemorySize, G_SMEM);
    cudaFuncSetAttribute(fattn, cudaFuncAttributeMaxDynamicSharedMemorySize, A_SMEM);

    const int PB = (int)((XQ + 4 * WQ) / 256);
    prep<<<PB, 256>>>(x, Wk, Wv, Ws, Wo);

    gemm3<<<dim3(24, CM / 128), 128, G_SMEM>>>();     // -> g_Kf, g_Vf, g_Sf

    fattn<<<dim3(CS / 64, CB * CH), 128, A_SMEM>>>(); // -> g_xf (=P+Sf fp16)

    gemm_out<<<dim3(CD / 128, CM / 128), 128, G_SMEM>>>(out);
}